// round 1
// baseline (speedup 1.0000x reference)
#include <cuda_runtime.h>
#include <cstdint>

#define NN 100000
#define EE 1600000
#define ET (EE + NN)

// ---------------- scratch (static device globals; no allocation) ----------------
__device__ float    g_t3[3][EE];      // per-edge attention scalar, per layer
__device__ float    g_tsum[3][NN];    // segment sum of t by dst -> becomes tself after div
__device__ int      g_cnt[NN];        // in-degree
__device__ float    g_h[NN * 64];     // h = x @ W
__device__ float    g_s[NN];          // h . a_src
__device__ float    g_d[NN];          // h . a_dst
__device__ float    g_alpha[ET];      // alpha, then exp(alpha - m)
__device__ unsigned g_m[NN];          // segment max (monotone-uint encoded)
__device__ float    g_denom[NN];      // softmax denom
__device__ float    g_accum[NN * 64]; // aggregation accumulator
__device__ float    g_x[NN * 64];     // layer output / next input
__device__ float    g_we[3][64];      // We[l] @ a_e

// ---------------- w_e[l] = We[l] @ a_e ----------------
__global__ void k_we(const float* __restrict__ We, const float* __restrict__ a_e) {
    int l = blockIdx.x, k = threadIdx.x;
    const float* w = We + l * 4096 + k * 64;
    const float* a = a_e + l * 64;
    float s = 0.f;
#pragma unroll
    for (int j = 0; j < 64; j++) s += w[j] * a[j];
    g_we[l][k] = s;
}

// ---------------- one pass over edge_attr: t_e^l for 3 layers + degree + segment sums ----------------
__global__ void k_edge_pre(const float* __restrict__ eattr, const int* __restrict__ ei) {
    __shared__ float we_s[3][64];
    int tid = threadIdx.x;
    if (tid < 192) ((float*)we_s)[tid] = ((const float*)g_we)[tid];
    __syncthreads();
    int lane = tid & 31;
    int e = (int)((blockIdx.x * (unsigned)blockDim.x + tid) >> 5);
    if (e >= EE) return;
    float2 v = ((const float2*)(eattr + (size_t)e * 64))[lane];
    float t0 = v.x * we_s[0][2 * lane] + v.y * we_s[0][2 * lane + 1];
    float t1 = v.x * we_s[1][2 * lane] + v.y * we_s[1][2 * lane + 1];
    float t2 = v.x * we_s[2][2 * lane] + v.y * we_s[2][2 * lane + 1];
#pragma unroll
    for (int o = 16; o > 0; o >>= 1) {
        t0 += __shfl_down_sync(0xffffffffu, t0, o);
        t1 += __shfl_down_sync(0xffffffffu, t1, o);
        t2 += __shfl_down_sync(0xffffffffu, t2, o);
    }
    if (lane == 0) {
        int dst = ei[EE + e];
        g_t3[0][e] = t0; g_t3[1][e] = t1; g_t3[2][e] = t2;
        atomicAdd(&g_tsum[0][dst], t0);
        atomicAdd(&g_tsum[1][dst], t1);
        atomicAdd(&g_tsum[2][dst], t2);
        atomicAdd(&g_cnt[dst], 1);
    }
}

// ---------------- tsum -> tself = tsum / max(cnt,1) ----------------
__global__ void k_selfdiv() {
    int n = blockIdx.x * blockDim.x + threadIdx.x;
    if (n >= NN) return;
    float inv = 1.f / fmaxf((float)g_cnt[n], 1.f);
    g_tsum[0][n] *= inv;
    g_tsum[1][n] *= inv;
    g_tsum[2][n] *= inv;
}

// ---------------- h = x @ W ; s = h.a_s ; d = h.a_d (fused) ----------------
__global__ void k_gemm(const float* __restrict__ x, const float* __restrict__ W,
                       const float* __restrict__ a_s, const float* __restrict__ a_d) {
    __shared__ float Ws[64 * 64];
    __shared__ float as_s[64], ad_s[64];
    int tid = threadIdx.x;
    for (int i = tid; i < 4096; i += blockDim.x) Ws[i] = W[i];
    if (tid < 64) { as_s[tid] = a_s[tid]; ad_s[tid] = a_d[tid]; }
    __syncthreads();
    int lane = tid & 31, wid = tid >> 5;
    int nwarps = gridDim.x * (blockDim.x >> 5);
    for (int row = blockIdx.x * (blockDim.x >> 5) + wid; row < NN; row += nwarps) {
        float x0 = x[(size_t)row * 64 + lane];
        float x1 = x[(size_t)row * 64 + 32 + lane];
        float h0 = 0.f, h1 = 0.f;
#pragma unroll
        for (int k = 0; k < 64; k++) {
            float xk = __shfl_sync(0xffffffffu, (k < 32) ? x0 : x1, k & 31);
            h0 += xk * Ws[k * 64 + lane];
            h1 += xk * Ws[k * 64 + 32 + lane];
        }
        g_h[(size_t)row * 64 + lane] = h0;
        g_h[(size_t)row * 64 + 32 + lane] = h1;
        float sv = h0 * as_s[lane] + h1 * as_s[lane + 32];
        float dv = h0 * ad_s[lane] + h1 * ad_s[lane + 32];
#pragma unroll
        for (int o = 16; o > 0; o >>= 1) {
            sv += __shfl_down_sync(0xffffffffu, sv, o);
            dv += __shfl_down_sync(0xffffffffu, dv, o);
        }
        if (lane == 0) { g_s[row] = sv; g_d[row] = dv; }
    }
}

__device__ __forceinline__ unsigned ford(float f) {
    unsigned u = __float_as_uint(f);
    return (u >> 31) ? ~u : (u | 0x80000000u);
}
__device__ __forceinline__ float funord(unsigned u) {
    return (u >> 31) ? __uint_as_float(u ^ 0x80000000u) : __uint_as_float(~u);
}

// ---------------- alpha = lrelu(s[src]+d[dst]+t) ; segment max ----------------
__global__ void k_alpha_max(const int* __restrict__ ei, int l) {
    int e = blockIdx.x * blockDim.x + threadIdx.x;
    if (e >= ET) return;
    int src, dst; float t;
    if (e < EE) { src = ei[e]; dst = ei[EE + e]; t = g_t3[l][e]; }
    else        { src = dst = e - EE; t = g_tsum[l][src]; }
    float a = g_s[src] + g_d[dst] + t;
    a = (a >= 0.f) ? a : 0.2f * a;
    g_alpha[e] = a;
    atomicMax(&g_m[dst], ford(a));
}

// ---------------- ea = exp(alpha - m[dst]) ; segment sum ----------------
__global__ void k_exp_sum(const int* __restrict__ ei) {
    int e = blockIdx.x * blockDim.x + threadIdx.x;
    if (e >= ET) return;
    int dst = (e < EE) ? ei[EE + e] : (e - EE);
    float m = funord(g_m[dst]);
    float ea = __expf(g_alpha[e] - m);
    g_alpha[e] = ea;
    atomicAdd(&g_denom[dst], ea);
}

// ---------------- out[dst] += (ea/denom[dst]) * h[src] ; 2 edges per warp, red.v4 ----------------
__global__ void k_agg(const int* __restrict__ ei) {
    int tid = blockIdx.x * blockDim.x + threadIdx.x;
    int lane = threadIdx.x & 31;
    int e = (tid >> 5) * 2 + (lane >> 4);
    if (e >= ET) return;
    int src, dst;
    if (e < EE) { src = ei[e]; dst = ei[EE + e]; }
    else        { src = dst = e - EE; }
    float coef = g_alpha[e] / g_denom[dst];
    int c = (lane & 15) * 4;
    float4 hv = *(const float4*)(g_h + (size_t)src * 64 + c);
    hv.x *= coef; hv.y *= coef; hv.z *= coef; hv.w *= coef;
    float* p = g_accum + (size_t)dst * 64 + c;
    asm volatile("red.global.add.v4.f32 [%0], {%1,%2,%3,%4};"
                 :: "l"(p), "f"(hv.x), "f"(hv.y), "f"(hv.z), "f"(hv.w) : "memory");
}

// ---------------- x_next = accum + bias (+ ReLU between layers) ----------------
__global__ void k_fin(const float* __restrict__ bias, float* __restrict__ dest, int dorelu) {
    int i = blockIdx.x * blockDim.x + threadIdx.x;
    if (i >= NN * 64) return;
    float v = g_accum[i] + bias[i & 63];
    if (dorelu) v = fmaxf(v, 0.f);
    dest[i] = v;
}

extern "C" void kernel_launch(void* const* d_in, const int* in_sizes, int n_in,
                              void* d_out, int out_size) {
    const float* node  = (const float*)d_in[0];
    const float* ehid  = (const float*)d_in[1];
    const float* eattr = (const float*)d_in[2];
    const int*   ei    = (const int*)d_in[3];
    const float* W     = (const float*)d_in[4];
    const float* We    = (const float*)d_in[5];
    const float* a_s   = (const float*)d_in[6];
    const float* a_d   = (const float*)d_in[7];
    const float* a_e   = (const float*)d_in[8];
    const float* bias  = (const float*)d_in[9];
    float* out = (float*)d_out;

    void *p_tsum, *p_cnt, *p_m, *p_denom, *p_accum, *p_x;
    cudaGetSymbolAddress(&p_tsum,  g_tsum);
    cudaGetSymbolAddress(&p_cnt,   g_cnt);
    cudaGetSymbolAddress(&p_m,     g_m);
    cudaGetSymbolAddress(&p_denom, g_denom);
    cudaGetSymbolAddress(&p_accum, g_accum);
    cudaGetSymbolAddress(&p_x,     g_x);

    cudaMemsetAsync(p_tsum, 0, sizeof(float) * 3 * NN, 0);
    cudaMemsetAsync(p_cnt,  0, sizeof(int) * NN, 0);

    k_we<<<3, 64>>>(We, a_e);
    k_edge_pre<<<EE / 8, 256>>>(eattr, ei);
    k_selfdiv<<<(NN + 255) / 256, 256>>>();

    const float* xin = node;
    for (int l = 0; l < 3; l++) {
        k_gemm<<<1024, 256>>>(xin, W + l * 4096, a_s + l * 64, a_d + l * 64);
        cudaMemsetAsync(p_m,     0, sizeof(unsigned) * NN, 0);
        cudaMemsetAsync(p_denom, 0, sizeof(float) * NN, 0);
        cudaMemsetAsync(p_accum, 0, sizeof(float) * NN * 64, 0);
        k_alpha_max<<<(ET + 255) / 256, 256>>>(ei, l);
        k_exp_sum<<<(ET + 255) / 256, 256>>>(ei);
        k_agg<<<(ET + 15) / 16, 256>>>(ei);
        float* dest = (l == 2) ? out : (float*)p_x;
        k_fin<<<(NN * 64 + 255) / 256, 256>>>(bias + l * 64, dest, l < 2);
        xin = (const float*)p_x;
    }

    // pass-through edge_hidden into second tuple slot
    cudaMemcpyAsync(out + (size_t)NN * 64, ehid, (size_t)EE * 64 * sizeof(float),
                    cudaMemcpyDeviceToDevice, 0);
}

// round 3
// speedup vs baseline: 1.0249x; 1.0249x over previous
#include <cuda_runtime.h>
#include <cstdint>

#define NN 100000
#define EE 1600000
#define ET (EE + NN)

// ---------------- scratch (static device globals; no allocation) ----------------
__device__ float    g_t3[3][EE];      // per-edge attention scalar, per layer
__device__ float    g_tsum[3][NN];    // segment sum of t by dst -> becomes tself after div
__device__ int      g_cnt[NN];        // in-degree
__device__ float    g_h[NN * 64];     // h = x @ W
__device__ float    g_s[NN];          // h . a_src
__device__ float    g_d[NN];          // h . a_dst
__device__ float    g_alpha[ET];      // exp(alpha)
__device__ float    g_denom[NN];      // softmax denom
__device__ float    g_x1[NN * 64];    // layer output ping
__device__ float    g_x2[NN * 64];    // layer output pong
__device__ float    g_we[3][64];      // We[l] @ a_e

// ---------------- w_e[l] = We[l] @ a_e ----------------
__global__ void k_we(const float* __restrict__ We, const float* __restrict__ a_e) {
    int l = blockIdx.x, k = threadIdx.x;
    const float* w = We + l * 4096 + k * 64;
    const float* a = a_e + l * 64;
    float s = 0.f;
#pragma unroll
    for (int j = 0; j < 64; j++) s += w[j] * a[j];
    g_we[l][k] = s;
}

// ---------------- one pass over edge_attr: t_e^l for 3 layers + degree + segment sums ----------------
__global__ void k_edge_pre(const float* __restrict__ eattr, const int* __restrict__ ei) {
    __shared__ float we_s[3][64];
    int tid = threadIdx.x;
    if (tid < 192) ((float*)we_s)[tid] = ((const float*)g_we)[tid];
    __syncthreads();
    int lane = tid & 31;
    int e = (int)((blockIdx.x * (unsigned)blockDim.x + tid) >> 5);
    if (e >= EE) return;
    float2 v = ((const float2*)(eattr + (size_t)e * 64))[lane];
    float t0 = v.x * we_s[0][2 * lane] + v.y * we_s[0][2 * lane + 1];
    float t1 = v.x * we_s[1][2 * lane] + v.y * we_s[1][2 * lane + 1];
    float t2 = v.x * we_s[2][2 * lane] + v.y * we_s[2][2 * lane + 1];
#pragma unroll
    for (int o = 16; o > 0; o >>= 1) {
        t0 += __shfl_down_sync(0xffffffffu, t0, o);
        t1 += __shfl_down_sync(0xffffffffu, t1, o);
        t2 += __shfl_down_sync(0xffffffffu, t2, o);
    }
    if (lane == 0) {
        int dst = ei[EE + e];
        g_t3[0][e] = t0; g_t3[1][e] = t1; g_t3[2][e] = t2;
        atomicAdd(&g_tsum[0][dst], t0);
        atomicAdd(&g_tsum[1][dst], t1);
        atomicAdd(&g_tsum[2][dst], t2);
        atomicAdd(&g_cnt[dst], 1);
    }
}

// ---------------- tsum -> tself = tsum / max(cnt,1) ----------------
__global__ void k_selfdiv() {
    int n = blockIdx.x * blockDim.x + threadIdx.x;
    if (n >= NN) return;
    float inv = 1.f / fmaxf((float)g_cnt[n], 1.f);
    g_tsum[0][n] *= inv;
    g_tsum[1][n] *= inv;
    g_tsum[2][n] *= inv;
}

// ---------------- h = relu?(x) @ W ; s = h.a_s ; d = h.a_d ----------------
// One 64-row tile per block; W + x tile in smem; 16 outputs per thread in regs.
__global__ __launch_bounds__(256) void k_gemm(const float* __restrict__ x,
                                              const float* __restrict__ W,
                                              const float* __restrict__ a_s,
                                              const float* __restrict__ a_d,
                                              int dorelu) {
    __shared__ float Ws[64 * 64];
    __shared__ float xs[64 * 65];
    __shared__ float as_s[64], ad_s[64];
    int tid = threadIdx.x;
#pragma unroll
    for (int i = 0; i < 16; i++) Ws[tid + i * 256] = W[tid + i * 256];
    if (tid < 64) { as_s[tid] = a_s[tid]; ad_s[tid] = a_d[tid]; }

    int base = blockIdx.x * 64;
    int rows = min(64, NN - base);
    // cooperative coalesced load of x tile (float4), optional relu
    for (int i = tid; i < rows * 16; i += 256) {
        int r = i >> 4, c4 = i & 15;
        float4 v = ((const float4*)(x + (size_t)(base + r) * 64))[c4];
        if (dorelu) {
            v.x = fmaxf(v.x, 0.f); v.y = fmaxf(v.y, 0.f);
            v.z = fmaxf(v.z, 0.f); v.w = fmaxf(v.w, 0.f);
        }
        float* p = xs + r * 65 + c4 * 4;
        p[0] = v.x; p[1] = v.y; p[2] = v.z; p[3] = v.w;
    }
    __syncthreads();

    int r = tid >> 2;          // 0..63
    int cg = (tid & 3) * 16;   // col group
    if (r < rows) {
        float acc[16];
#pragma unroll
        for (int j = 0; j < 16; j++) acc[j] = 0.f;
#pragma unroll
        for (int k = 0; k < 64; k++) {
            float xv = xs[r * 65 + k];
            const float4* wrow = (const float4*)(Ws + k * 64 + cg);
#pragma unroll
            for (int j4 = 0; j4 < 4; j4++) {
                float4 w = wrow[j4];
                acc[j4 * 4 + 0] += xv * w.x;
                acc[j4 * 4 + 1] += xv * w.y;
                acc[j4 * 4 + 2] += xv * w.z;
                acc[j4 * 4 + 3] += xv * w.w;
            }
        }
        float4* hp = (float4*)(g_h + (size_t)(base + r) * 64 + cg);
#pragma unroll
        for (int j4 = 0; j4 < 4; j4++)
            hp[j4] = make_float4(acc[j4 * 4], acc[j4 * 4 + 1], acc[j4 * 4 + 2], acc[j4 * 4 + 3]);
        float sv = 0.f, dv = 0.f;
#pragma unroll
        for (int j = 0; j < 16; j++) {
            sv += acc[j] * as_s[cg + j];
            dv += acc[j] * ad_s[cg + j];
        }
        sv += __shfl_down_sync(0xffffffffu, sv, 2);
        dv += __shfl_down_sync(0xffffffffu, dv, 2);
        sv += __shfl_down_sync(0xffffffffu, sv, 1);
        dv += __shfl_down_sync(0xffffffffu, dv, 1);
        if ((tid & 3) == 0) { g_s[base + r] = sv; g_d[base + r] = dv; }
    }
}

// ---------------- dest = broadcast bias (pre-fill aggregation target) ----------------
__global__ void k_fill_bias(float* __restrict__ dest, const float* __restrict__ bias) {
    int i = blockIdx.x * blockDim.x + threadIdx.x;
    if (i >= NN * 16) return;
    float4 v = ((const float4*)bias)[i & 15];
    ((float4*)dest)[i] = v;
}

// ---------------- ea = exp(lrelu(s[src]+d[dst]+t)) ; segment sum (no max: shift-invariant) ----------------
__global__ void k_alpha_exp(const int* __restrict__ ei, int l) {
    int e = blockIdx.x * blockDim.x + threadIdx.x;
    if (e >= ET) return;
    int src, dst; float t;
    if (e < EE) { src = ei[e]; dst = ei[EE + e]; t = g_t3[l][e]; }
    else        { src = dst = e - EE; t = g_tsum[l][src]; }
    float a = g_s[src] + g_d[dst] + t;
    a = (a >= 0.f) ? a : 0.2f * a;
    float ea = __expf(a);
    g_alpha[e] = ea;
    atomicAdd(&g_denom[dst], ea);
}

// ---------------- dest[dst] += (ea/denom[dst]) * h[src] ; 2 edges/warp, red.v4 ----------------
__global__ void k_agg(const int* __restrict__ ei, float* __restrict__ dest) {
    int tid = blockIdx.x * blockDim.x + threadIdx.x;
    int lane = threadIdx.x & 31;
    int e = (tid >> 5) * 2 + (lane >> 4);
    if (e >= ET) return;
    int src, dst;
    if (e < EE) { src = ei[e]; dst = ei[EE + e]; }
    else        { src = dst = e - EE; }
    float coef = g_alpha[e] / g_denom[dst];
    int c = (lane & 15) * 4;
    float4 hv = *(const float4*)(g_h + (size_t)src * 64 + c);
    hv.x *= coef; hv.y *= coef; hv.z *= coef; hv.w *= coef;
    float* p = dest + (size_t)dst * 64 + c;
    asm volatile("red.global.add.v4.f32 [%0], {%1,%2,%3,%4};"
                 :: "l"(p), "f"(hv.x), "f"(hv.y), "f"(hv.z), "f"(hv.w) : "memory");
}

extern "C" void kernel_launch(void* const* d_in, const int* in_sizes, int n_in,
                              void* d_out, int out_size) {
    const float* node  = (const float*)d_in[0];
    const float* ehid  = (const float*)d_in[1];
    const float* eattr = (const float*)d_in[2];
    const int*   ei    = (const int*)d_in[3];
    const float* W     = (const float*)d_in[4];
    const float* We    = (const float*)d_in[5];
    const float* a_s   = (const float*)d_in[6];
    const float* a_d   = (const float*)d_in[7];
    const float* a_e   = (const float*)d_in[8];
    const float* bias  = (const float*)d_in[9];
    float* out = (float*)d_out;

    void *p_tsum, *p_cnt, *p_denom, *p_x1, *p_x2;
    cudaGetSymbolAddress(&p_tsum,  g_tsum);
    cudaGetSymbolAddress(&p_cnt,   g_cnt);
    cudaGetSymbolAddress(&p_denom, g_denom);
    cudaGetSymbolAddress(&p_x1,    g_x1);
    cudaGetSymbolAddress(&p_x2,    g_x2);

    cudaMemsetAsync(p_tsum, 0, sizeof(float) * 3 * NN, 0);
    cudaMemsetAsync(p_cnt,  0, sizeof(int) * NN, 0);

    k_we<<<3, 64>>>(We, a_e);
    k_edge_pre<<<EE / 8, 256>>>(eattr, ei);
    k_selfdiv<<<(NN + 255) / 256, 256>>>();

    const float* xin = node;
    float* dests[3] = { (float*)p_x1, (float*)p_x2, out };
    for (int l = 0; l < 3; l++) {
        float* dest = dests[l];
        k_gemm<<<(NN + 63) / 64, 256>>>(xin, W + l * 4096, a_s + l * 64, a_d + l * 64, l > 0);
        cudaMemsetAsync(p_denom, 0, sizeof(float) * NN, 0);
        k_fill_bias<<<(NN * 16 + 255) / 256, 256>>>(dest, bias + l * 64);
        k_alpha_exp<<<(ET + 255) / 256, 256>>>(ei, l);
        k_agg<<<(ET + 15) / 16, 256>>>(ei, dest);
        xin = dest;
    }

    // pass-through edge_hidden into second tuple slot
    cudaMemcpyAsync(out + (size_t)NN * 64, ehid, (size_t)EE * 64 * sizeof(float),
                    cudaMemcpyDeviceToDevice, 0);
}

// round 4
// speedup vs baseline: 1.2897x; 1.2583x over previous
#include <cuda_runtime.h>
#include <cstdint>

#define NN 100000
#define EE 1600000
#define ET (EE + NN)

// ---------------- scratch (static device globals; no allocation) ----------------
__device__ float g_t3[3][EE];      // per-edge attention scalar, per layer
__device__ float g_tsum[3][NN];    // segment sum of t by dst -> tself after div
__device__ int   g_cnt[NN];        // in-degree
__device__ float g_h[NN * 64];     // h = x' @ W
__device__ float g_s[NN];          // x' . (W a_s)
__device__ float g_d[NN];          // x' . (W a_d)
__device__ float g_denom[NN];      // softmax denom
__device__ float g_x1[NN * 64];    // raw accum ping
__device__ float g_x2[NN * 64];    // raw accum pong
__device__ float g_we[3][64];      // We @ a_e
__device__ float g_ws[3][64];      // W  @ a_s
__device__ float g_wd[3][64];      // W  @ a_d

// ---------------- per-layer projected attention vectors ----------------
__global__ void k_prep(const float* __restrict__ We, const float* __restrict__ W,
                       const float* __restrict__ a_e, const float* __restrict__ a_s,
                       const float* __restrict__ a_d) {
    int l = blockIdx.x, k = threadIdx.x;
    const float* wer = We + l * 4096 + k * 64;
    const float* wr  = W  + l * 4096 + k * 64;
    float se = 0.f, ss = 0.f, sd = 0.f;
#pragma unroll
    for (int j = 0; j < 64; j++) {
        se += wer[j] * a_e[l * 64 + j];
        ss += wr[j]  * a_s[l * 64 + j];
        sd += wr[j]  * a_d[l * 64 + j];
    }
    g_we[l][k] = se; g_ws[l][k] = ss; g_wd[l][k] = sd;
}

// ---------------- one pass over edge_attr: t_e^l for 3 layers + degree + segment sums ----------------
__global__ void k_edge_pre(const float* __restrict__ eattr, const int* __restrict__ ei) {
    __shared__ float we_s[3][64];
    int tid = threadIdx.x;
    if (tid < 192) ((float*)we_s)[tid] = ((const float*)g_we)[tid];
    __syncthreads();
    int lane = tid & 31;
    int e = (int)((blockIdx.x * (unsigned)blockDim.x + tid) >> 5);
    if (e >= EE) return;
    float2 v = ((const float2*)(eattr + (size_t)e * 64))[lane];
    float t0 = v.x * we_s[0][2 * lane] + v.y * we_s[0][2 * lane + 1];
    float t1 = v.x * we_s[1][2 * lane] + v.y * we_s[1][2 * lane + 1];
    float t2 = v.x * we_s[2][2 * lane] + v.y * we_s[2][2 * lane + 1];
#pragma unroll
    for (int o = 16; o > 0; o >>= 1) {
        t0 += __shfl_down_sync(0xffffffffu, t0, o);
        t1 += __shfl_down_sync(0xffffffffu, t1, o);
        t2 += __shfl_down_sync(0xffffffffu, t2, o);
    }
    if (lane == 0) {
        int dst = ei[EE + e];
        g_t3[0][e] = t0; g_t3[1][e] = t1; g_t3[2][e] = t2;
        atomicAdd(&g_tsum[0][dst], t0);
        atomicAdd(&g_tsum[1][dst], t1);
        atomicAdd(&g_tsum[2][dst], t2);
        atomicAdd(&g_cnt[dst], 1);
    }
}

__global__ void k_selfdiv() {
    int n = blockIdx.x * blockDim.x + threadIdx.x;
    if (n >= NN) return;
    float inv = 1.f / fmaxf((float)g_cnt[n], 1.f);
    g_tsum[0][n] *= inv;
    g_tsum[1][n] *= inv;
    g_tsum[2][n] *= inv;
}

// ---------------- h = x' @ W ; s = x'.ws ; d = x'.wd ----------------
// x' = transform ? relu(x/denom + prev_bias) : x.  128-row tile, 8x4 outputs/thread.
__global__ __launch_bounds__(256) void k_gemm(const float* __restrict__ x,
                                              const float* __restrict__ W,
                                              const float* __restrict__ wsv,
                                              const float* __restrict__ wdv,
                                              const float* __restrict__ prev_bias,
                                              int transform) {
    __shared__ float Ws[64 * 64];
    __shared__ float xs[128][68];
    __shared__ float wss[64], wds[64];
    int tid = threadIdx.x;
#pragma unroll
    for (int i = 0; i < 16; i++) Ws[tid + i * 256] = W[tid + i * 256];
    if (tid < 64) { wss[tid] = wsv[tid]; wds[tid] = wdv[tid]; }

    int base = blockIdx.x * 128;
    int rows = min(128, NN - base);
    for (int i = tid; i < rows * 16; i += 256) {
        int r = i >> 4, c4 = i & 15;
        float4 v = ((const float4*)(x + (size_t)(base + r) * 64))[c4];
        if (transform) {
            float inv = 1.f / g_denom[base + r];
            float4 b = ((const float4*)prev_bias)[c4];
            v.x = fmaxf(v.x * inv + b.x, 0.f);
            v.y = fmaxf(v.y * inv + b.y, 0.f);
            v.z = fmaxf(v.z * inv + b.z, 0.f);
            v.w = fmaxf(v.w * inv + b.w, 0.f);
        }
        float* p = &xs[r][c4 * 4];
        p[0] = v.x; p[1] = v.y; p[2] = v.z; p[3] = v.w;
    }
    __syncthreads();

    int rg = tid >> 4;          // 0..15 -> rows rg*8 .. rg*8+7
    int cg = (tid & 15) * 4;    // cols cg .. cg+3
    float acc[8][4];
#pragma unroll
    for (int j = 0; j < 8; j++) {
        acc[j][0] = 0.f; acc[j][1] = 0.f; acc[j][2] = 0.f; acc[j][3] = 0.f;
    }
#pragma unroll 8
    for (int k = 0; k < 64; k++) {
        float4 w = *(const float4*)(Ws + k * 64 + cg);
#pragma unroll
        for (int j = 0; j < 8; j++) {
            float xv = xs[rg * 8 + j][k];
            acc[j][0] += xv * w.x;
            acc[j][1] += xv * w.y;
            acc[j][2] += xv * w.z;
            acc[j][3] += xv * w.w;
        }
    }
#pragma unroll
    for (int j = 0; j < 8; j++) {
        int r = rg * 8 + j;
        if (r < rows)
            *(float4*)(g_h + (size_t)(base + r) * 64 + cg) =
                make_float4(acc[j][0], acc[j][1], acc[j][2], acc[j][3]);
    }
    // s, d from the (already transformed) x tile
    if (tid < 128 && tid < rows) {
        float sv = 0.f, dv = 0.f;
#pragma unroll 16
        for (int k = 0; k < 64; k++) {
            float xv = xs[tid][k];
            sv += xv * wss[k];
            dv += xv * wds[k];
        }
        g_s[base + tid] = sv;
        g_d[base + tid] = dv;
    }
}

// ---------------- fused edge pass: ea = exp(lrelu(s+d+t)); denom += ea; accum[dst] += ea*h[src] ----------------
__global__ __launch_bounds__(256) void k_edge(const int* __restrict__ ei,
                                              float* __restrict__ accum, int l) {
    int gtid = blockIdx.x * 256 + threadIdx.x;
    int lane = threadIdx.x & 31;
    int hl = lane & 15;
    int e = (gtid >> 5) * 2 + (lane >> 4);
    if (e >= ET) return;
    int src, dst; float t;
    if (e < EE) { src = ei[e]; dst = ei[EE + e]; t = g_t3[l][e]; }
    else        { src = dst = e - EE; t = g_tsum[l][src]; }
    float a = g_s[src] + g_d[dst] + t;
    a = (a >= 0.f) ? a : 0.2f * a;
    float ea = __expf(a);
    if (hl == 0) atomicAdd(&g_denom[dst], ea);
    float4 hv = *(const float4*)(g_h + (size_t)src * 64 + hl * 4);
    hv.x *= ea; hv.y *= ea; hv.z *= ea; hv.w *= ea;
    float* p = accum + (size_t)dst * 64 + hl * 4;
    asm volatile("red.global.add.v4.f32 [%0], {%1,%2,%3,%4};"
                 :: "l"(p), "f"(hv.x), "f"(hv.y), "f"(hv.z), "f"(hv.w) : "memory");
}

// ---------------- final: out = out/denom + bias (in place over raw accum) ----------------
__global__ void k_fin(float* __restrict__ out, const float* __restrict__ bias) {
    int i = blockIdx.x * blockDim.x + threadIdx.x;
    if (i >= NN * 16) return;
    int node = i >> 4;
    float inv = 1.f / g_denom[node];
    float4 v = ((float4*)out)[i];
    float4 b = ((const float4*)bias)[i & 15];
    v.x = v.x * inv + b.x;
    v.y = v.y * inv + b.y;
    v.z = v.z * inv + b.z;
    v.w = v.w * inv + b.w;
    ((float4*)out)[i] = v;
}

extern "C" void kernel_launch(void* const* d_in, const int* in_sizes, int n_in,
                              void* d_out, int out_size) {
    const float* node  = (const float*)d_in[0];
    const float* ehid  = (const float*)d_in[1];
    const float* eattr = (const float*)d_in[2];
    const int*   ei    = (const int*)d_in[3];
    const float* W     = (const float*)d_in[4];
    const float* We    = (const float*)d_in[5];
    const float* a_s   = (const float*)d_in[6];
    const float* a_d   = (const float*)d_in[7];
    const float* a_e   = (const float*)d_in[8];
    const float* bias  = (const float*)d_in[9];
    float* out = (float*)d_out;

    void *p_tsum, *p_cnt, *p_denom, *p_x1, *p_x2, *p_ws, *p_wd;
    cudaGetSymbolAddress(&p_tsum,  g_tsum);
    cudaGetSymbolAddress(&p_cnt,   g_cnt);
    cudaGetSymbolAddress(&p_denom, g_denom);
    cudaGetSymbolAddress(&p_x1,    g_x1);
    cudaGetSymbolAddress(&p_x2,    g_x2);
    cudaGetSymbolAddress(&p_ws,    g_ws);
    cudaGetSymbolAddress(&p_wd,    g_wd);

    cudaMemsetAsync(p_tsum, 0, sizeof(float) * 3 * NN, 0);
    cudaMemsetAsync(p_cnt,  0, sizeof(int) * NN, 0);

    k_prep<<<3, 64>>>(We, W, a_e, a_s, a_d);
    k_edge_pre<<<EE / 8, 256>>>(eattr, ei);
    k_selfdiv<<<(NN + 255) / 256, 256>>>();

    const float* xin = node;
    float* dests[3] = { (float*)p_x1, (float*)p_x2, out };
    for (int l = 0; l < 3; l++) {
        float* dest = dests[l];
        // gemm consumes previous layer's denom (for l>0) BEFORE it is reset
        k_gemm<<<(NN + 127) / 128, 256>>>(xin, W + l * 4096,
                                          (const float*)p_ws + l * 64,
                                          (const float*)p_wd + l * 64,
                                          bias + (l > 0 ? (l - 1) * 64 : 0), l > 0);
        cudaMemsetAsync(p_denom, 0, sizeof(float) * NN, 0);
        cudaMemsetAsync(dest, 0, sizeof(float) * NN * 64, 0);
        k_edge<<<(ET + 15) / 16, 256>>>(ei, dest, l);
        xin = dest;
    }
    k_fin<<<(NN * 16 + 255) / 256, 256>>>(out, bias + 2 * 64);

    // pass-through edge_hidden into second tuple slot
    cudaMemcpyAsync(out + (size_t)NN * 64, ehid, (size_t)EE * 64 * sizeof(float),
                    cudaMemcpyDeviceToDevice, 0);
}

// round 6
// speedup vs baseline: 1.2936x; 1.0030x over previous
#include <cuda_runtime.h>
#include <cstdint>

#define NN 100000
#define EE 1600000
#define ET (EE + NN)

// ---------------- scratch (static device globals; no allocation) ----------------
__device__ float g_t3[3][EE];      // per-edge attention scalar, per layer
__device__ float g_tsum[3][NN];    // segment sum of t by dst -> tself after div
__device__ int   g_cnt[NN];        // in-degree
__device__ float g_h[NN * 64];     // h = x' @ W
__device__ float g_s[NN];          // x' . (W a_s)
__device__ float g_d[NN];          // x' . (W a_d)
__device__ float g_denom[NN];      // softmax denom
__device__ float g_x1[NN * 64];    // raw accum ping
__device__ float g_x2[NN * 64];    // raw accum pong
__device__ float g_we[3][64];      // We @ a_e
__device__ float g_ws[3][64];      // W  @ a_s
__device__ float g_wd[3][64];      // W  @ a_d

// ---------------- per-layer projected attention vectors ----------------
__global__ void k_prep(const float* __restrict__ We, const float* __restrict__ W,
                       const float* __restrict__ a_e, const float* __restrict__ a_s,
                       const float* __restrict__ a_d) {
    int l = blockIdx.x, k = threadIdx.x;
    const float* wer = We + l * 4096 + k * 64;
    const float* wr  = W  + l * 4096 + k * 64;
    float se = 0.f, ss = 0.f, sd = 0.f;
#pragma unroll
    for (int j = 0; j < 64; j++) {
        se += wer[j] * a_e[l * 64 + j];
        ss += wr[j]  * a_s[l * 64 + j];
        sd += wr[j]  * a_d[l * 64 + j];
    }
    g_we[l][k] = se; g_ws[l][k] = ss; g_wd[l][k] = sd;
}

// ---------------- one pass over edge_attr: t_e^l for 3 layers + degree + segment sums ----------------
__global__ void k_edge_pre(const float* __restrict__ eattr, const int* __restrict__ ei) {
    __shared__ float we_s[3][64];
    int tid = threadIdx.x;
    if (tid < 192) ((float*)we_s)[tid] = ((const float*)g_we)[tid];
    __syncthreads();
    int lane = tid & 31;
    int e = (int)((blockIdx.x * (unsigned)blockDim.x + tid) >> 5);
    if (e >= EE) return;
    float2 v = ((const float2*)(eattr + (size_t)e * 64))[lane];
    float t0 = v.x * we_s[0][2 * lane] + v.y * we_s[0][2 * lane + 1];
    float t1 = v.x * we_s[1][2 * lane] + v.y * we_s[1][2 * lane + 1];
    float t2 = v.x * we_s[2][2 * lane] + v.y * we_s[2][2 * lane + 1];
#pragma unroll
    for (int o = 16; o > 0; o >>= 1) {
        t0 += __shfl_down_sync(0xffffffffu, t0, o);
        t1 += __shfl_down_sync(0xffffffffu, t1, o);
        t2 += __shfl_down_sync(0xffffffffu, t2, o);
    }
    if (lane == 0) {
        int dst = ei[EE + e];
        g_t3[0][e] = t0; g_t3[1][e] = t1; g_t3[2][e] = t2;
        atomicAdd(&g_tsum[0][dst], t0);
        atomicAdd(&g_tsum[1][dst], t1);
        atomicAdd(&g_tsum[2][dst], t2);
        atomicAdd(&g_cnt[dst], 1);
    }
}

__global__ void k_selfdiv() {
    int n = blockIdx.x * blockDim.x + threadIdx.x;
    if (n >= NN) return;
    float inv = 1.f / fmaxf((float)g_cnt[n], 1.f);
    g_tsum[0][n] *= inv;
    g_tsum[1][n] *= inv;
    g_tsum[2][n] *= inv;
}

// ---------------- h = x' @ W ; s = x'.ws ; d = x'.wd ----------------
// x' = transform ? relu(x/denom + prev_bias) : x.  128-row tile, 8x4 outputs/thread.
__global__ __launch_bounds__(256) void k_gemm(const float* __restrict__ x,
                                              const float* __restrict__ W,
                                              const float* __restrict__ wsv,
                                              const float* __restrict__ wdv,
                                              const float* __restrict__ prev_bias,
                                              int transform) {
    __shared__ float Ws[64 * 64];
    __shared__ float xs[128][68];
    __shared__ float wss[64], wds[64];
    int tid = threadIdx.x;
#pragma unroll
    for (int i = 0; i < 16; i++) Ws[tid + i * 256] = W[tid + i * 256];
    if (tid < 64) { wss[tid] = wsv[tid]; wds[tid] = wdv[tid]; }

    int base = blockIdx.x * 128;
    int rows = min(128, NN - base);
    for (int i = tid; i < rows * 16; i += 256) {
        int r = i >> 4, c4 = i & 15;
        float4 v = ((const float4*)(x + (size_t)(base + r) * 64))[c4];
        if (transform) {
            float inv = 1.f / g_denom[base + r];
            float4 b = ((const float4*)prev_bias)[c4];
            v.x = fmaxf(v.x * inv + b.x, 0.f);
            v.y = fmaxf(v.y * inv + b.y, 0.f);
            v.z = fmaxf(v.z * inv + b.z, 0.f);
            v.w = fmaxf(v.w * inv + b.w, 0.f);
        }
        float* p = &xs[r][c4 * 4];
        p[0] = v.x; p[1] = v.y; p[2] = v.z; p[3] = v.w;
    }
    __syncthreads();

    int rg = tid >> 4;          // 0..15 -> rows rg*8 .. rg*8+7
    int cg = (tid & 15) * 4;    // cols cg .. cg+3
    float acc[8][4];
#pragma unroll
    for (int j = 0; j < 8; j++) {
        acc[j][0] = 0.f; acc[j][1] = 0.f; acc[j][2] = 0.f; acc[j][3] = 0.f;
    }
#pragma unroll 8
    for (int k = 0; k < 64; k++) {
        float4 w = *(const float4*)(Ws + k * 64 + cg);
#pragma unroll
        for (int j = 0; j < 8; j++) {
            float xv = xs[rg * 8 + j][k];
            acc[j][0] += xv * w.x;
            acc[j][1] += xv * w.y;
            acc[j][2] += xv * w.z;
            acc[j][3] += xv * w.w;
        }
    }
#pragma unroll
    for (int j = 0; j < 8; j++) {
        int r = rg * 8 + j;
        if (r < rows)
            *(float4*)(g_h + (size_t)(base + r) * 64 + cg) =
                make_float4(acc[j][0], acc[j][1], acc[j][2], acc[j][3]);
    }
    // s, d from the (already transformed) x tile
    if (tid < 128 && tid < rows) {
        float sv = 0.f, dv = 0.f;
#pragma unroll 16
        for (int k = 0; k < 64; k++) {
            float xv = xs[tid][k];
            sv += xv * wss[k];
            dv += xv * wds[k];
        }
        g_s[base + tid] = sv;
        g_d[base + tid] = dv;
    }
}

// ---------------- fused edge pass: ea = exp(lrelu(s+d+t)); denom += ea; accum[dst] += ea*h[src] ----------------
__global__ __launch_bounds__(256) void k_edge(const int* __restrict__ ei,
                                              float* __restrict__ accum, int l) {
    int gtid = blockIdx.x * 256 + threadIdx.x;
    int lane = threadIdx.x & 31;
    int hl = lane & 15;
    int e = (gtid >> 5) * 2 + (lane >> 4);
    if (e >= ET) return;
    int src, dst; float t;
    if (e < EE) { src = ei[e]; dst = ei[EE + e]; t = g_t3[l][e]; }
    else        { src = dst = e - EE; t = g_tsum[l][src]; }
    float a = g_s[src] + g_d[dst] + t;
    a = (a >= 0.f) ? a : 0.2f * a;
    float ea = __expf(a);
    if (hl == 0) atomicAdd(&g_denom[dst], ea);
    float4 hv = *(const float4*)(g_h + (size_t)src * 64 + hl * 4);
    hv.x *= ea; hv.y *= ea; hv.z *= ea; hv.w *= ea;
    float* p = accum + (size_t)dst * 64 + hl * 4;
    asm volatile("red.global.add.v4.f32 [%0], {%1,%2,%3,%4};"
                 :: "l"(p), "f"(hv.x), "f"(hv.y), "f"(hv.z), "f"(hv.w) : "memory");
}

// ---------------- final: out = out/denom + bias (in place over raw accum) ----------------
__global__ void k_fin(float* __restrict__ out, const float* __restrict__ bias) {
    int i = blockIdx.x * blockDim.x + threadIdx.x;
    if (i >= NN * 16) return;
    int node = i >> 4;
    float inv = 1.f / g_denom[node];
    float4 v = ((float4*)out)[i];
    float4 b = ((const float4*)bias)[i & 15];
    v.x = v.x * inv + b.x;
    v.y = v.y * inv + b.y;
    v.z = v.z * inv + b.z;
    v.w = v.w * inv + b.w;
    ((float4*)out)[i] = v;
}

extern "C" void kernel_launch(void* const* d_in, const int* in_sizes, int n_in,
                              void* d_out, int out_size) {
    const float* node  = (const float*)d_in[0];
    const float* ehid  = (const float*)d_in[1];
    const float* eattr = (const float*)d_in[2];
    const int*   ei    = (const int*)d_in[3];
    const float* W     = (const float*)d_in[4];
    const float* We    = (const float*)d_in[5];
    const float* a_s   = (const float*)d_in[6];
    const float* a_d   = (const float*)d_in[7];
    const float* a_e   = (const float*)d_in[8];
    const float* bias  = (const float*)d_in[9];
    float* out = (float*)d_out;

    // one-time host-side resources (no device memory involved)
    static cudaStream_t s_copy = nullptr;
    static cudaEvent_t ev_fork = nullptr, ev_join = nullptr;
    if (s_copy == nullptr) {
        cudaStreamCreateWithFlags(&s_copy, cudaStreamNonBlocking);
        cudaEventCreateWithFlags(&ev_fork, cudaEventDisableTiming);
        cudaEventCreateWithFlags(&ev_join, cudaEventDisableTiming);
    }

    void *p_tsum, *p_cnt, *p_denom, *p_x1, *p_x2, *p_ws, *p_wd;
    cudaGetSymbolAddress(&p_tsum,  g_tsum);
    cudaGetSymbolAddress(&p_cnt,   g_cnt);
    cudaGetSymbolAddress(&p_denom, g_denom);
    cudaGetSymbolAddress(&p_x1,    g_x1);
    cudaGetSymbolAddress(&p_x2,    g_x2);
    cudaGetSymbolAddress(&p_ws,    g_ws);
    cudaGetSymbolAddress(&p_wd,    g_wd);

    // fork: edge_hidden pass-through copy runs concurrently with all compute
    cudaEventRecord(ev_fork, 0);
    cudaStreamWaitEvent(s_copy, ev_fork, 0);
    cudaMemcpyAsync(out + (size_t)NN * 64, ehid, (size_t)EE * 64 * sizeof(float),
                    cudaMemcpyDeviceToDevice, s_copy);

    cudaMemsetAsync(p_tsum, 0, sizeof(float) * 3 * NN, 0);
    cudaMemsetAsync(p_cnt,  0, sizeof(int) * NN, 0);

    k_prep<<<3, 64>>>(We, W, a_e, a_s, a_d);
    k_edge_pre<<<EE / 8, 256>>>(eattr, ei);
    k_selfdiv<<<(NN + 255) / 256, 256>>>();

    const float* xin = node;
    float* dests[3] = { (float*)p_x1, (float*)p_x2, out };
    for (int l = 0; l < 3; l++) {
        float* dest = dests[l];
        // gemm consumes previous layer's denom (for l>0) BEFORE it is reset
        k_gemm<<<(NN + 127) / 128, 256>>>(xin, W + l * 4096,
                                          (const float*)p_ws + l * 64,
                                          (const float*)p_wd + l * 64,
                                          bias + (l > 0 ? (l - 1) * 64 : 0), l > 0);
        cudaMemsetAsync(p_denom, 0, sizeof(float) * NN, 0);
        cudaMemsetAsync(dest, 0, sizeof(float) * NN * 64, 0);
        k_edge<<<(ET + 15) / 16, 256>>>(ei, dest, l);
        xin = dest;
    }
    k_fin<<<(NN * 16 + 255) / 256, 256>>>(out, bias + 2 * 64);

    // join: copy must be done before the graph completes
    cudaEventRecord(ev_join, s_copy);
    cudaStreamWaitEvent(0, ev_join, 0);
}

// round 7
// speedup vs baseline: 1.3026x; 1.0070x over previous
#include <cuda_runtime.h>
#include <cstdint>

#define NN 100000
#define EE 1600000
#define ET (EE + NN)

// ---------------- scratch (static device globals; no allocation) ----------------
__device__ float g_t3[3][EE];      // per-edge attention scalar, per layer
__device__ float g_tsum[3][NN];    // segment sum of t by dst -> tself after div
__device__ int   g_cnt[NN];        // in-degree
__device__ float g_h[NN * 64];     // h = x' @ W
__device__ float g_s[NN];          // x' . (W a_s)
__device__ float g_d[NN];          // x' . (W a_d)
__device__ float g_denom[NN];      // softmax denom
__device__ float g_x1[NN * 64];    // raw accum ping
__device__ float g_x2[NN * 64];    // raw accum pong
__device__ float g_we[3][64];      // We @ a_e
__device__ float g_ws[3][64];      // W  @ a_s
__device__ float g_wd[3][64];      // W  @ a_d

// ---------------- per-layer projected attention vectors ----------------
__global__ void k_prep(const float* __restrict__ We, const float* __restrict__ W,
                       const float* __restrict__ a_e, const float* __restrict__ a_s,
                       const float* __restrict__ a_d) {
    int l = blockIdx.x, k = threadIdx.x;
    const float* wer = We + l * 4096 + k * 64;
    const float* wr  = W  + l * 4096 + k * 64;
    float se = 0.f, ss = 0.f, sd = 0.f;
#pragma unroll
    for (int j = 0; j < 64; j++) {
        se += wer[j] * a_e[l * 64 + j];
        ss += wr[j]  * a_s[l * 64 + j];
        sd += wr[j]  * a_d[l * 64 + j];
    }
    g_we[l][k] = se; g_ws[l][k] = ss; g_wd[l][k] = sd;
}

// ---------------- one pass over edge_attr: t_e^l for 3 layers + degree + segment sums ----------------
__global__ void k_edge_pre(const float* __restrict__ eattr, const int* __restrict__ ei) {
    __shared__ float we_s[3][64];
    int tid = threadIdx.x;
    if (tid < 192) ((float*)we_s)[tid] = ((const float*)g_we)[tid];
    __syncthreads();
    int lane = tid & 31;
    int e = (int)((blockIdx.x * (unsigned)blockDim.x + tid) >> 5);
    if (e >= EE) return;
    float2 v = ((const float2*)(eattr + (size_t)e * 64))[lane];
    float t0 = v.x * we_s[0][2 * lane] + v.y * we_s[0][2 * lane + 1];
    float t1 = v.x * we_s[1][2 * lane] + v.y * we_s[1][2 * lane + 1];
    float t2 = v.x * we_s[2][2 * lane] + v.y * we_s[2][2 * lane + 1];
#pragma unroll
    for (int o = 16; o > 0; o >>= 1) {
        t0 += __shfl_down_sync(0xffffffffu, t0, o);
        t1 += __shfl_down_sync(0xffffffffu, t1, o);
        t2 += __shfl_down_sync(0xffffffffu, t2, o);
    }
    if (lane == 0) {
        int dst = ei[EE + e];
        g_t3[0][e] = t0; g_t3[1][e] = t1; g_t3[2][e] = t2;
        atomicAdd(&g_tsum[0][dst], t0);
        atomicAdd(&g_tsum[1][dst], t1);
        atomicAdd(&g_tsum[2][dst], t2);
        atomicAdd(&g_cnt[dst], 1);
    }
}

__global__ void k_selfdiv() {
    int n = blockIdx.x * blockDim.x + threadIdx.x;
    if (n >= NN) return;
    float inv = 1.f / fmaxf((float)g_cnt[n], 1.f);
    g_tsum[0][n] *= inv;
    g_tsum[1][n] *= inv;
    g_tsum[2][n] *= inv;
}

// ---------------- h = x' @ W ; s = x'.ws ; d = x'.wd ----------------
// x' = transform ? relu(x/denom + prev_bias) : x.  128-row tile, 8x4 outputs/thread.
__global__ __launch_bounds__(256) void k_gemm(const float* __restrict__ x,
                                              const float* __restrict__ W,
                                              const float* __restrict__ wsv,
                                              const float* __restrict__ wdv,
                                              const float* __restrict__ prev_bias,
                                              int transform) {
    __shared__ float Ws[64 * 64];
    __shared__ float xs[128][68];
    __shared__ float wss[64], wds[64];
    int tid = threadIdx.x;
#pragma unroll
    for (int i = 0; i < 16; i++) Ws[tid + i * 256] = W[tid + i * 256];
    if (tid < 64) { wss[tid] = wsv[tid]; wds[tid] = wdv[tid]; }

    int base = blockIdx.x * 128;
    int rows = min(128, NN - base);
    for (int i = tid; i < rows * 16; i += 256) {
        int r = i >> 4, c4 = i & 15;
        float4 v = ((const float4*)(x + (size_t)(base + r) * 64))[c4];
        if (transform) {
            float inv = 1.f / g_denom[base + r];
            float4 b = ((const float4*)prev_bias)[c4];
            v.x = fmaxf(v.x * inv + b.x, 0.f);
            v.y = fmaxf(v.y * inv + b.y, 0.f);
            v.z = fmaxf(v.z * inv + b.z, 0.f);
            v.w = fmaxf(v.w * inv + b.w, 0.f);
        }
        float* p = &xs[r][c4 * 4];
        p[0] = v.x; p[1] = v.y; p[2] = v.z; p[3] = v.w;
    }
    __syncthreads();

    int rg = tid >> 4;          // 0..15 -> rows rg*8 .. rg*8+7
    int cg = (tid & 15) * 4;    // cols cg .. cg+3
    float acc[8][4];
#pragma unroll
    for (int j = 0; j < 8; j++) {
        acc[j][0] = 0.f; acc[j][1] = 0.f; acc[j][2] = 0.f; acc[j][3] = 0.f;
    }
#pragma unroll 8
    for (int k = 0; k < 64; k++) {
        float4 w = *(const float4*)(Ws + k * 64 + cg);
#pragma unroll
        for (int j = 0; j < 8; j++) {
            float xv = xs[rg * 8 + j][k];
            acc[j][0] += xv * w.x;
            acc[j][1] += xv * w.y;
            acc[j][2] += xv * w.z;
            acc[j][3] += xv * w.w;
        }
    }
#pragma unroll
    for (int j = 0; j < 8; j++) {
        int r = rg * 8 + j;
        if (r < rows)
            *(float4*)(g_h + (size_t)(base + r) * 64 + cg) =
                make_float4(acc[j][0], acc[j][1], acc[j][2], acc[j][3]);
    }
    // s, d from the (already transformed) x tile
    if (tid < 128 && tid < rows) {
        float sv = 0.f, dv = 0.f;
#pragma unroll 16
        for (int k = 0; k < 64; k++) {
            float xv = xs[tid][k];
            sv += xv * wss[k];
            dv += xv * wds[k];
        }
        g_s[base + tid] = sv;
        g_d[base + tid] = dv;
    }
}

// ---------------- fused edge pass: ea = exp(lrelu(s+d+t)); denom += ea; accum[dst] += ea*h[src] ----------------
__global__ __launch_bounds__(256) void k_edge(const int* __restrict__ ei,
                                              float* __restrict__ accum, int l) {
    int gtid = blockIdx.x * 256 + threadIdx.x;
    int lane = threadIdx.x & 31;
    int hl = lane & 15;
    int e = (gtid >> 5) * 2 + (lane >> 4);
    if (e >= ET) return;
    int src, dst; float t;
    if (e < EE) { src = ei[e]; dst = ei[EE + e]; t = g_t3[l][e]; }
    else        { src = dst = e - EE; t = g_tsum[l][src]; }
    float a = g_s[src] + g_d[dst] + t;
    a = (a >= 0.f) ? a : 0.2f * a;
    float ea = __expf(a);
    if (hl == 0) atomicAdd(&g_denom[dst], ea);
    float4 hv = *(const float4*)(g_h + (size_t)src * 64 + hl * 4);
    hv.x *= ea; hv.y *= ea; hv.z *= ea; hv.w *= ea;
    float* p = accum + (size_t)dst * 64 + hl * 4;
    asm volatile("red.global.add.v4.f32 [%0], {%1,%2,%3,%4};"
                 :: "l"(p), "f"(hv.x), "f"(hv.y), "f"(hv.z), "f"(hv.w) : "memory");
}

// ---------------- final: out = out/denom + bias (in place over raw accum) ----------------
__global__ void k_fin(float* __restrict__ out, const float* __restrict__ bias) {
    int i = blockIdx.x * blockDim.x + threadIdx.x;
    if (i >= NN * 16) return;
    int node = i >> 4;
    float inv = 1.f / g_denom[node];
    float4 v = ((float4*)out)[i];
    float4 b = ((const float4*)bias)[i & 15];
    v.x = v.x * inv + b.x;
    v.y = v.y * inv + b.y;
    v.z = v.z * inv + b.z;
    v.w = v.w * inv + b.w;
    ((float4*)out)[i] = v;
}

// ---------------- SM-driven pass-through copy (co-schedules with compute branch) ----------------
__global__ __launch_bounds__(256) void k_copy(const float4* __restrict__ src,
                                              float4* __restrict__ dst, int n) {
    int i = blockIdx.x * 256 + threadIdx.x;
    int stride = gridDim.x * 256;
    for (; i < n; i += stride) dst[i] = src[i];
}

extern "C" void kernel_launch(void* const* d_in, const int* in_sizes, int n_in,
                              void* d_out, int out_size) {
    const float* node  = (const float*)d_in[0];
    const float* ehid  = (const float*)d_in[1];
    const float* eattr = (const float*)d_in[2];
    const int*   ei    = (const int*)d_in[3];
    const float* W     = (const float*)d_in[4];
    const float* We    = (const float*)d_in[5];
    const float* a_s   = (const float*)d_in[6];
    const float* a_d   = (const float*)d_in[7];
    const float* a_e   = (const float*)d_in[8];
    const float* bias  = (const float*)d_in[9];
    float* out = (float*)d_out;

    // one-time host-side resources (no device memory involved)
    static cudaStream_t s_copy = nullptr;
    static cudaEvent_t ev_fork = nullptr, ev_join = nullptr;
    if (s_copy == nullptr) {
        cudaStreamCreateWithFlags(&s_copy, cudaStreamNonBlocking);
        cudaEventCreateWithFlags(&ev_fork, cudaEventDisableTiming);
        cudaEventCreateWithFlags(&ev_join, cudaEventDisableTiming);
    }

    void *p_tsum, *p_cnt, *p_denom, *p_x1, *p_x2, *p_ws, *p_wd;
    cudaGetSymbolAddress(&p_tsum,  g_tsum);
    cudaGetSymbolAddress(&p_cnt,   g_cnt);
    cudaGetSymbolAddress(&p_denom, g_denom);
    cudaGetSymbolAddress(&p_x1,    g_x1);
    cudaGetSymbolAddress(&p_x2,    g_x2);
    cudaGetSymbolAddress(&p_ws,    g_ws);
    cudaGetSymbolAddress(&p_wd,    g_wd);

    // fork: edge_hidden pass-through copy (SM kernel) runs concurrently with compute
    cudaEventRecord(ev_fork, 0);
    cudaStreamWaitEvent(s_copy, ev_fork, 0);
    k_copy<<<2048, 256, 0, s_copy>>>((const float4*)ehid,
                                     (float4*)(out + (size_t)NN * 64),
                                     EE * 16);

    cudaMemsetAsync(p_tsum, 0, sizeof(float) * 3 * NN, 0);
    cudaMemsetAsync(p_cnt,  0, sizeof(int) * NN, 0);

    k_prep<<<3, 64>>>(We, W, a_e, a_s, a_d);
    k_edge_pre<<<EE / 8, 256>>>(eattr, ei);
    k_selfdiv<<<(NN + 255) / 256, 256>>>();

    const float* xin = node;
    float* dests[3] = { (float*)p_x1, (float*)p_x2, out };
    for (int l = 0; l < 3; l++) {
        float* dest = dests[l];
        // gemm consumes previous layer's denom (for l>0) BEFORE it is reset
        k_gemm<<<(NN + 127) / 128, 256>>>(xin, W + l * 4096,
                                          (const float*)p_ws + l * 64,
                                          (const float*)p_wd + l * 64,
                                          bias + (l > 0 ? (l - 1) * 64 : 0), l > 0);
        cudaMemsetAsync(p_denom, 0, sizeof(float) * NN, 0);
        cudaMemsetAsync(dest, 0, sizeof(float) * NN * 64, 0);
        k_edge<<<(ET + 15) / 16, 256>>>(ei, dest, l);
        xin = dest;
    }
    k_fin<<<(NN * 16 + 255) / 256, 256>>>(out, bias + 2 * 64);

    // join: copy must be done before the graph completes
    cudaEventRecord(ev_join, s_copy);
    cudaStreamWaitEvent(0, ev_join, 0);
}

// round 8
// speedup vs baseline: 1.6837x; 1.2925x over previous
#include <cuda_runtime.h>
#include <cstdint>

#define NN 100000
#define EE 1600000
#define NB_SCAN 391   // ceil(NN/256)

// ---------------- scratch (static device globals; no allocation) ----------------
__device__ int    g_cnt[NN];
__device__ int    g_off[NN + 1];
__device__ int    g_cursor[NN];
__device__ int    g_bsum[512];
__device__ float4 g_csr[EE];       // {src_as_float, t0, t1, t2} grouped by dst
__device__ float  g_h[NN * 64];    // h = x' @ W
__device__ float  g_s[NN];         // x' . (W a_s)
__device__ float  g_d[NN];         // x' . (W a_d)
__device__ float  g_x1[NN * 64];   // layer output ping
__device__ float  g_x2[NN * 64];   // layer output pong
__device__ float  g_we[3][64];     // We @ a_e
__device__ float  g_ws[3][64];     // W  @ a_s
__device__ float  g_wd[3][64];     // W  @ a_d

// ---------------- per-layer projected attention vectors ----------------
__global__ void k_prep(const float* __restrict__ We, const float* __restrict__ W,
                       const float* __restrict__ a_e, const float* __restrict__ a_s,
                       const float* __restrict__ a_d) {
    int l = blockIdx.x, k = threadIdx.x;
    const float* wer = We + l * 4096 + k * 64;
    const float* wr  = W  + l * 4096 + k * 64;
    float se = 0.f, ss = 0.f, sd = 0.f;
#pragma unroll
    for (int j = 0; j < 64; j++) {
        se += wer[j] * a_e[l * 64 + j];
        ss += wr[j]  * a_s[l * 64 + j];
        sd += wr[j]  * a_d[l * 64 + j];
    }
    g_we[l][k] = se; g_ws[l][k] = ss; g_wd[l][k] = sd;
}

// ---------------- in-degree histogram ----------------
__global__ void k_hist(const int* __restrict__ ei) {
    int e = blockIdx.x * 256 + threadIdx.x;
    if (e < EE) atomicAdd(&g_cnt[ei[EE + e]], 1);
}

// ---------------- exclusive prefix scan of g_cnt -> g_off (3 kernels) ----------------
__global__ void k_scan_block() {
    int t = threadIdx.x, i = blockIdx.x * 256 + t;
    int v = (i < NN) ? g_cnt[i] : 0;
    int lane = t & 31, w = t >> 5;
    int incl = v;
#pragma unroll
    for (int o = 1; o < 32; o <<= 1) {
        int n = __shfl_up_sync(0xffffffffu, incl, o);
        if (lane >= o) incl += n;
    }
    __shared__ int wt[8];
    if (lane == 31) wt[w] = incl;
    __syncthreads();
    if (t < 8) {
        int x = wt[t], ix = x;
#pragma unroll
        for (int o = 1; o < 8; o <<= 1) {
            int n = __shfl_up_sync(0xffu, ix, o);
            if (t >= o) ix += n;
        }
        wt[t] = ix - x;   // exclusive warp base
    }
    __syncthreads();
    int excl = incl - v + wt[w];
    if (i < NN) g_off[i] = excl;
    if (t == 255) g_bsum[blockIdx.x] = excl + v;
}

__global__ void k_scan_top(int nb) {
    __shared__ int sm[512];
    int t = threadIdx.x;
    sm[t] = (t < nb) ? g_bsum[t] : 0;
    __syncthreads();
    for (int o = 1; o < 512; o <<= 1) {
        int v = (t >= o) ? sm[t - o] : 0;
        __syncthreads();
        sm[t] += v;
        __syncthreads();
    }
    int ex = (t == 0) ? 0 : sm[t - 1];
    if (t < nb) g_bsum[t] = ex;
}

__global__ void k_scan_add() {
    int i = blockIdx.x * 256 + threadIdx.x;
    if (i < NN) {
        int o = g_off[i] + g_bsum[blockIdx.x];
        g_off[i] = o;
        g_cursor[i] = o;
    }
    if (i == 0) g_off[NN] = EE;
}

// ---------------- edge scan: t_e for 3 layers, scatter packed CSR record ----------------
__global__ void k_edge_pre(const float* __restrict__ eattr, const int* __restrict__ ei) {
    __shared__ float we_s[3][64];
    int tid = threadIdx.x;
    if (tid < 192) ((float*)we_s)[tid] = ((const float*)g_we)[tid];
    __syncthreads();
    int lane = tid & 31;
    int e = (int)((blockIdx.x * (unsigned)blockDim.x + tid) >> 5);
    if (e >= EE) return;
    float2 v = ((const float2*)(eattr + (size_t)e * 64))[lane];
    float t0 = v.x * we_s[0][2 * lane] + v.y * we_s[0][2 * lane + 1];
    float t1 = v.x * we_s[1][2 * lane] + v.y * we_s[1][2 * lane + 1];
    float t2 = v.x * we_s[2][2 * lane] + v.y * we_s[2][2 * lane + 1];
#pragma unroll
    for (int o = 16; o > 0; o >>= 1) {
        t0 += __shfl_down_sync(0xffffffffu, t0, o);
        t1 += __shfl_down_sync(0xffffffffu, t1, o);
        t2 += __shfl_down_sync(0xffffffffu, t2, o);
    }
    if (lane == 0) {
        int dst = ei[EE + e];
        int pos = atomicAdd(&g_cursor[dst], 1);
        g_csr[pos] = make_float4(__int_as_float(ei[e]), t0, t1, t2);
    }
}

// ---------------- h = x' @ W ; s = x'.ws ; d = x'.wd ;  x' = dorelu ? relu(x) : x ----------------
__global__ __launch_bounds__(256) void k_gemm(const float* __restrict__ x,
                                              const float* __restrict__ W,
                                              const float* __restrict__ wsv,
                                              const float* __restrict__ wdv,
                                              int dorelu) {
    __shared__ float Ws[64 * 64];
    __shared__ float xs[128][68];
    __shared__ float wss[64], wds[64];
    int tid = threadIdx.x;
#pragma unroll
    for (int i = 0; i < 16; i++) Ws[tid + i * 256] = W[tid + i * 256];
    if (tid < 64) { wss[tid] = wsv[tid]; wds[tid] = wdv[tid]; }

    int base = blockIdx.x * 128;
    int rows = min(128, NN - base);
    for (int i = tid; i < rows * 16; i += 256) {
        int r = i >> 4, c4 = i & 15;
        float4 v = ((const float4*)(x + (size_t)(base + r) * 64))[c4];
        if (dorelu) {
            v.x = fmaxf(v.x, 0.f); v.y = fmaxf(v.y, 0.f);
            v.z = fmaxf(v.z, 0.f); v.w = fmaxf(v.w, 0.f);
        }
        float* p = &xs[r][c4 * 4];
        p[0] = v.x; p[1] = v.y; p[2] = v.z; p[3] = v.w;
    }
    __syncthreads();

    int rg = tid >> 4;          // rows rg*8 .. rg*8+7
    int cg = (tid & 15) * 4;    // cols cg .. cg+3
    float acc[8][4];
#pragma unroll
    for (int j = 0; j < 8; j++) {
        acc[j][0] = 0.f; acc[j][1] = 0.f; acc[j][2] = 0.f; acc[j][3] = 0.f;
    }
#pragma unroll 8
    for (int k = 0; k < 64; k++) {
        float4 w = *(const float4*)(Ws + k * 64 + cg);
#pragma unroll
        for (int j = 0; j < 8; j++) {
            float xv = xs[rg * 8 + j][k];
            acc[j][0] += xv * w.x;
            acc[j][1] += xv * w.y;
            acc[j][2] += xv * w.z;
            acc[j][3] += xv * w.w;
        }
    }
#pragma unroll
    for (int j = 0; j < 8; j++) {
        int r = rg * 8 + j;
        if (r < rows)
            *(float4*)(g_h + (size_t)(base + r) * 64 + cg) =
                make_float4(acc[j][0], acc[j][1], acc[j][2], acc[j][3]);
    }
    if (tid < 128 && tid < rows) {
        float sv = 0.f, dv = 0.f;
#pragma unroll 16
        for (int k = 0; k < 64; k++) {
            float xv = xs[tid][k];
            sv += xv * wss[k];
            dv += xv * wds[k];
        }
        g_s[base + tid] = sv;
        g_d[base + tid] = dv;
    }
}

// ---------------- CSR aggregation: half-warp per node, register accumulation, no atomics ----------------
__global__ __launch_bounds__(256) void k_agg(float* __restrict__ dest,
                                             const float* __restrict__ bias, int l) {
    int tid = threadIdx.x;
    int node = blockIdx.x * 16 + (tid >> 4);
    if (node >= NN) return;
    int hl = tid & 15;
    int hb = tid & 16;                      // half-warp base within warp
    unsigned mask = 0xFFFFu << hb;

    int beg = g_off[node], end = g_off[node + 1];
    float dn = g_d[node];
    float4 acc = make_float4(0.f, 0.f, 0.f, 0.f);
    float denomp = 0.f, tsump = 0.f;

    for (int chunk = beg; chunk < end; chunk += 16) {
        int e = chunk + hl;
        int srcv = 0; float ea = 0.f, tv = 0.f;
        if (e < end) {
            float4 c = g_csr[e];
            srcv = __float_as_int(c.x);
            tv = (l == 0) ? c.y : ((l == 1) ? c.z : c.w);
            float a = g_s[srcv] + dn + tv;
            a = (a >= 0.f) ? a : 0.2f * a;
            ea = __expf(a);
        }
        denomp += ea;
        tsump  += tv;
        int lim = min(16, end - chunk);
        for (int j = 0; j < lim; j++) {
            int   sj = __shfl_sync(mask, srcv, hb + j);
            float ej = __shfl_sync(mask, ea,   hb + j);
            float4 hv = *(const float4*)(g_h + (size_t)sj * 64 + hl * 4);
            acc.x += ej * hv.x; acc.y += ej * hv.y;
            acc.z += ej * hv.z; acc.w += ej * hv.w;
        }
    }
    // butterfly-reduce partials across the half-warp (all lanes get totals)
#pragma unroll
    for (int o = 8; o > 0; o >>= 1) {
        denomp += __shfl_xor_sync(mask, denomp, o);
        tsump  += __shfl_xor_sync(mask, tsump,  o);
    }
    // self loop: t_self = mean of incoming t (0 if deg==0)
    int deg = end - beg;
    float tself = tsump / fmaxf((float)deg, 1.f);
    float a = g_s[node] + dn + tself;
    a = (a >= 0.f) ? a : 0.2f * a;
    float eas = __expf(a);
    float4 hv = *(const float4*)(g_h + (size_t)node * 64 + hl * 4);
    acc.x += eas * hv.x; acc.y += eas * hv.y;
    acc.z += eas * hv.z; acc.w += eas * hv.w;
    float inv = 1.f / (denomp + eas);
    float4 b = ((const float4*)bias)[hl];
    ((float4*)(dest + (size_t)node * 64))[hl] =
        make_float4(acc.x * inv + b.x, acc.y * inv + b.y,
                    acc.z * inv + b.z, acc.w * inv + b.w);
}

// ---------------- SM-driven pass-through copy (side-stream branch) ----------------
__global__ __launch_bounds__(256) void k_copy(const float4* __restrict__ src,
                                              float4* __restrict__ dst, int n) {
    int i = blockIdx.x * 256 + threadIdx.x;
    int stride = gridDim.x * 256;
    for (; i < n; i += stride) dst[i] = src[i];
}

extern "C" void kernel_launch(void* const* d_in, const int* in_sizes, int n_in,
                              void* d_out, int out_size) {
    const float* node  = (const float*)d_in[0];
    const float* ehid  = (const float*)d_in[1];
    const float* eattr = (const float*)d_in[2];
    const int*   ei    = (const int*)d_in[3];
    const float* W     = (const float*)d_in[4];
    const float* We    = (const float*)d_in[5];
    const float* a_s   = (const float*)d_in[6];
    const float* a_d   = (const float*)d_in[7];
    const float* a_e   = (const float*)d_in[8];
    const float* bias  = (const float*)d_in[9];
    float* out = (float*)d_out;

    static cudaStream_t s_copy = nullptr;
    static cudaEvent_t ev_fork = nullptr, ev_join = nullptr;
    if (s_copy == nullptr) {
        cudaStreamCreateWithFlags(&s_copy, cudaStreamNonBlocking);
        cudaEventCreateWithFlags(&ev_fork, cudaEventDisableTiming);
        cudaEventCreateWithFlags(&ev_join, cudaEventDisableTiming);
    }

    void *p_cnt, *p_x1, *p_x2, *p_ws, *p_wd;
    cudaGetSymbolAddress(&p_cnt, g_cnt);
    cudaGetSymbolAddress(&p_x1,  g_x1);
    cudaGetSymbolAddress(&p_x2,  g_x2);
    cudaGetSymbolAddress(&p_ws,  g_ws);
    cudaGetSymbolAddress(&p_wd,  g_wd);

    // fork: pass-through copy runs on a parallel graph branch
    cudaEventRecord(ev_fork, 0);
    cudaStreamWaitEvent(s_copy, ev_fork, 0);
    k_copy<<<2048, 256, 0, s_copy>>>((const float4*)ehid,
                                     (float4*)(out + (size_t)NN * 64),
                                     EE * 16);

    cudaMemsetAsync(p_cnt, 0, sizeof(int) * NN, 0);

    k_hist<<<(EE + 255) / 256, 256>>>(ei);
    k_scan_block<<<NB_SCAN, 256>>>();
    k_scan_top<<<1, 512>>>(NB_SCAN);
    k_scan_add<<<NB_SCAN, 256>>>();
    k_prep<<<3, 64>>>(We, W, a_e, a_s, a_d);
    k_edge_pre<<<EE / 8, 256>>>(eattr, ei);

    const float* xin = node;
    float* dests[3] = { (float*)p_x1, (float*)p_x2, out };
    for (int l = 0; l < 3; l++) {
        float* dest = dests[l];
        k_gemm<<<(NN + 127) / 128, 256>>>(xin, W + l * 4096,
                                          (const float*)p_ws + l * 64,
                                          (const float*)p_wd + l * 64, l > 0);
        k_agg<<<(NN + 15) / 16, 256>>>(dest, bias + l * 64, l);
        xin = dest;
    }

    cudaEventRecord(ev_join, s_copy);
    cudaStreamWaitEvent(0, ev_join, 0);
}